// round 2
// baseline (speedup 1.0000x reference)
#include <cuda_runtime.h>
#include <cstddef>

#define S_  1024
#define P_  1024
#define J_  2048
#define B_  4
#define E_  1024
#define H_  16
#define I_  64
#define HI_ 1024

// ---------------- scratch (static device arrays; no runtime allocation) ----
__device__ float g_q[(size_t)S_ * B_ * HI_];          // (S,B,H*I)
__device__ float g_kv[(size_t)J_ * B_ * 2 * HI_];     // (J,B,2*H*I)  keys | values
__device__ float g_p[(size_t)J_ * HI_];               // (J,H*I)
__device__ float g_sc[(size_t)B_ * H_ * S_ * J_];     // (B*H, S, J) logits -> probs
__device__ float g_awv[(size_t)S_ * B_ * HI_];        // (S,B,H*I)
__device__ float g_o[(size_t)S_ * B_ * E_];           // pre-LN output

// ---------------- generic 128x128x8 SGEMM, row-major, optional residual ----
__global__ __launch_bounds__(256) void sgemm128(const float* __restrict__ A,
                                                const float* __restrict__ Bm,
                                                const float* __restrict__ res,
                                                float* __restrict__ C,
                                                int M, int N, int K) {
    __shared__ float As[8][128];
    __shared__ float Bs[8][128];
    int tid = threadIdx.x;
    int tx = tid & 15, ty = tid >> 4;
    int row0 = blockIdx.y * 128, col0 = blockIdx.x * 128;
    int arow = tid >> 1, acol = (tid & 1) << 2;
    int brow = tid >> 5, bcol = (tid & 31) << 2;
    const float* Ap = A + (size_t)(row0 + arow) * K + acol;
    const float* Bp = Bm + (size_t)brow * N + col0 + bcol;
    float acc[8][8];
#pragma unroll
    for (int i = 0; i < 8; i++)
#pragma unroll
        for (int j = 0; j < 8; j++) acc[i][j] = 0.f;

    for (int k0 = 0; k0 < K; k0 += 8) {
        float4 av = *(const float4*)(Ap + k0);
        float4 bv = *(const float4*)(Bp + (size_t)k0 * N);
        __syncthreads();
        As[acol + 0][arow] = av.x;
        As[acol + 1][arow] = av.y;
        As[acol + 2][arow] = av.z;
        As[acol + 3][arow] = av.w;
        *(float4*)&Bs[brow][bcol] = bv;
        __syncthreads();
#pragma unroll
        for (int kk = 0; kk < 8; kk++) {
            float a[8], b[8];
            *(float4*)(a)     = *(const float4*)&As[kk][ty << 2];
            *(float4*)(a + 4) = *(const float4*)&As[kk][64 + (ty << 2)];
            *(float4*)(b)     = *(const float4*)&Bs[kk][tx << 2];
            *(float4*)(b + 4) = *(const float4*)&Bs[kk][64 + (tx << 2)];
#pragma unroll
            for (int i = 0; i < 8; i++)
#pragma unroll
                for (int j = 0; j < 8; j++)
                    acc[i][j] = fmaf(a[i], b[j], acc[i][j]);
        }
    }
#pragma unroll
    for (int qi = 0; qi < 2; qi++)
#pragma unroll
        for (int r = 0; r < 4; r++) {
            int m = row0 + qi * 64 + (ty << 2) + r;
#pragma unroll
            for (int qj = 0; qj < 2; qj++) {
                int n = col0 + qj * 64 + (tx << 2);
                float4 vv;
                vv.x = acc[qi * 4 + r][qj * 4 + 0];
                vv.y = acc[qi * 4 + r][qj * 4 + 1];
                vv.z = acc[qi * 4 + r][qj * 4 + 2];
                vv.w = acc[qi * 4 + r][qj * 4 + 3];
                if (res) {
                    float4 rv = *(const float4*)&res[(size_t)m * N + n];
                    vv.x += rv.x; vv.y += rv.y; vv.z += rv.z; vv.w += rv.w;
                }
                *(float4*)&C[(size_t)m * N + n] = vv;
            }
        }
}

// ---------------- scores: content + rel-shifted position, mask, scale ------
// logits[bh,s,j] = ((q+u)·K[j] + (q+v)·p[j-s+S-1]) * 0.125 for j<=P+s else -1e30
#define SC_SMEM_FLOATS (2 * 64 * 65 + 128 * 65 + 64)
#define SC_SMEM_BYTES  (SC_SMEM_FLOATS * 4)

__global__ __launch_bounds__(256) void scores_kernel(const float* __restrict__ u,
                                                     const float* __restrict__ vvec) {
    int bh = blockIdx.z;
    int b = bh >> 4, h = bh & 15;
    int s0 = blockIdx.y << 6, j0 = blockIdx.x << 6;
    int tid = threadIdx.x;
    float* out = g_sc + ((size_t)bh * S_ + s0) * J_ + j0;

    if (j0 > P_ + s0 + 63) {  // tile entirely masked
        float4 m4 = make_float4(-1e30f, -1e30f, -1e30f, -1e30f);
#pragma unroll
        for (int it = 0; it < 4; it++) {
            int idx = it * 256 + tid;
            int r = idx >> 4, c = (idx & 15) << 2;
            *(float4*)&out[(size_t)r * J_ + c] = m4;
        }
        return;
    }

    extern __shared__ float sm[];
    float* qu_s = sm;                          // 64 x 65 (row-padded)
    float* K_s  = sm + 64 * 65;                // 64 x 65
    float* p_s  = sm + 2 * 64 * 65;            // 128 x 65
    float* w_s  = sm + 2 * 64 * 65 + 128 * 65; // 64 : (v - u)

    if (tid < 64) w_s[tid] = vvec[h * 64 + tid] - u[h * 64 + tid];

#pragma unroll
    for (int it = 0; it < 4; it++) {
        int idx = it * 256 + tid;
        int r = idx >> 4, i4 = (idx & 15) << 2;
        float4 q4 = *(const float4*)&g_q[((size_t)(s0 + r) * B_ + b) * HI_ + h * 64 + i4];
        float4 u4 = *(const float4*)&u[h * 64 + i4];
        qu_s[r * 65 + i4 + 0] = q4.x + u4.x;
        qu_s[r * 65 + i4 + 1] = q4.y + u4.y;
        qu_s[r * 65 + i4 + 2] = q4.z + u4.z;
        qu_s[r * 65 + i4 + 3] = q4.w + u4.w;
        float4 k4 = *(const float4*)&g_kv[((size_t)(j0 + r) * B_ + b) * (2 * HI_) + h * 64 + i4];
        K_s[r * 65 + i4 + 0] = k4.x;
        K_s[r * 65 + i4 + 1] = k4.y;
        K_s[r * 65 + i4 + 2] = k4.z;
        K_s[r * 65 + i4 + 3] = k4.w;
    }
    int d0 = j0 - s0 + 960;  // p row for local (ss=63+... d = d0 + (jj-ss+63)... window start)
#pragma unroll
    for (int it = 0; it < 8; it++) {
        int idx = it * 256 + tid;
        int r = idx >> 4, i4 = (idx & 15) << 2;
        int d = d0 + r;
        float4 p4 = make_float4(0.f, 0.f, 0.f, 0.f);
        if (d >= 0 && d < J_)
            p4 = *(const float4*)&g_p[(size_t)d * HI_ + h * 64 + i4];
        p_s[r * 65 + i4 + 0] = p4.x;
        p_s[r * 65 + i4 + 1] = p4.y;
        p_s[r * 65 + i4 + 2] = p4.z;
        p_s[r * 65 + i4 + 3] = p4.w;
    }
    __syncthreads();

    int tx = tid & 15, ty = tid >> 4;
    float acc[4][4];
#pragma unroll
    for (int r = 0; r < 4; r++)
#pragma unroll
        for (int c = 0; c < 4; c++) acc[r][c] = 0.f;

    int pb = (tx << 2) - (ty << 2) + 60;  // p_s row base; d_local = pb + (c-r+3)

    for (int i = 0; i < 64; i++) {
        float a[4], av[4], k[4], pv[7];
        float w = w_s[i];
#pragma unroll
        for (int r = 0; r < 4; r++) {
            a[r] = qu_s[((ty << 2) + r) * 65 + i];
            av[r] = a[r] + w;
        }
#pragma unroll
        for (int c = 0; c < 4; c++) k[c] = K_s[((tx << 2) + c) * 65 + i];
#pragma unroll
        for (int d = 0; d < 7; d++) pv[d] = p_s[(pb + d) * 65 + i];
#pragma unroll
        for (int r = 0; r < 4; r++)
#pragma unroll
            for (int c = 0; c < 4; c++)
                acc[r][c] = fmaf(a[r], k[c], fmaf(av[r], pv[c - r + 3], acc[r][c]));
    }

#pragma unroll
    for (int r = 0; r < 4; r++) {
        int s = s0 + (ty << 2) + r;
        int jb = j0 + (tx << 2);
        float4 o4;
        float* po = (float*)&o4;
#pragma unroll
        for (int c = 0; c < 4; c++)
            po[c] = (jb + c <= P_ + s) ? acc[r][c] * 0.125f : -1e30f;
        *(float4*)&out[(size_t)((ty << 2) + r) * J_ + (tx << 2)] = o4;
    }
}

// ---------------- row softmax over J=2048 ----------------------------------
__global__ __launch_bounds__(256) void softmax_kernel() {
    float* row = g_sc + ((size_t)blockIdx.y * S_ + blockIdx.x) * J_;
    int tid = threadIdx.x;
    float4 v0 = *(float4*)&row[tid * 8];
    float4 v1 = *(float4*)&row[tid * 8 + 4];
    float m = fmaxf(fmaxf(fmaxf(v0.x, v0.y), fmaxf(v0.z, v0.w)),
                    fmaxf(fmaxf(v1.x, v1.y), fmaxf(v1.z, v1.w)));
    __shared__ float red[8];
#pragma unroll
    for (int o = 16; o > 0; o >>= 1) m = fmaxf(m, __shfl_xor_sync(0xffffffffu, m, o));
    if ((tid & 31) == 0) red[tid >> 5] = m;
    __syncthreads();
    m = red[0];
#pragma unroll
    for (int i = 1; i < 8; i++) m = fmaxf(m, red[i]);

    v0.x = __expf(v0.x - m); v0.y = __expf(v0.y - m);
    v0.z = __expf(v0.z - m); v0.w = __expf(v0.w - m);
    v1.x = __expf(v1.x - m); v1.y = __expf(v1.y - m);
    v1.z = __expf(v1.z - m); v1.w = __expf(v1.w - m);
    float s = v0.x + v0.y + v0.z + v0.w + v1.x + v1.y + v1.z + v1.w;
    __syncthreads();
#pragma unroll
    for (int o = 16; o > 0; o >>= 1) s += __shfl_xor_sync(0xffffffffu, s, o);
    if ((tid & 31) == 0) red[tid >> 5] = s;
    __syncthreads();
    s = 0.f;
#pragma unroll
    for (int i = 0; i < 8; i++) s += red[i];
    float inv = 1.0f / s;
    v0.x *= inv; v0.y *= inv; v0.z *= inv; v0.w *= inv;
    v1.x *= inv; v1.y *= inv; v1.z *= inv; v1.w *= inv;
    *(float4*)&row[tid * 8] = v0;
    *(float4*)&row[tid * 8 + 4] = v1;
}

// ---------------- awv = probs @ V  (per b,h; skip all-zero key tiles) ------
__global__ __launch_bounds__(256) void awv_kernel() {
    int bh = blockIdx.y;
    int b = bh >> 4, h = bh & 15;
    int s0 = blockIdx.x << 7;
    int tid = threadIdx.x;
    int tx = tid & 15, ty = tid >> 4;
    __shared__ float Ps[16 * 132];  // [j][s] transposed
    __shared__ float Vs[16 * 68];   // [j][i]
    float acc[8][4];
#pragma unroll
    for (int r = 0; r < 8; r++)
#pragma unroll
        for (int c = 0; c < 4; c++) acc[r][c] = 0.f;

    const float* Prow = g_sc + ((size_t)bh * S_ + s0) * J_;
    int kmax = P_ + s0 + 128;  // probs are exactly 0 beyond this (<= J_)

    for (int j0 = 0; j0 < kmax; j0 += 16) {
        __syncthreads();
#pragma unroll
        for (int it = 0; it < 2; it++) {
            int idx = it * 256 + tid;
            int sr = idx >> 2, j4 = (idx & 3) << 2;
            float4 p4 = *(const float4*)&Prow[(size_t)sr * J_ + j0 + j4];
            Ps[(j4 + 0) * 132 + sr] = p4.x;
            Ps[(j4 + 1) * 132 + sr] = p4.y;
            Ps[(j4 + 2) * 132 + sr] = p4.z;
            Ps[(j4 + 3) * 132 + sr] = p4.w;
        }
        {
            int jr = tid >> 4, i4 = (tid & 15) << 2;
            float4 v4 = *(const float4*)&g_kv[((size_t)(j0 + jr) * B_ + b) * (2 * HI_) + HI_ + h * 64 + i4];
            *(float4*)&Vs[jr * 68 + i4] = v4;
        }
        __syncthreads();
#pragma unroll
        for (int jj = 0; jj < 16; jj++) {
            float a[8], bb[4];
            *(float4*)(a)     = *(const float4*)&Ps[jj * 132 + (ty << 3)];
            *(float4*)(a + 4) = *(const float4*)&Ps[jj * 132 + (ty << 3) + 4];
            *(float4*)(bb)    = *(const float4*)&Vs[jj * 68 + (tx << 2)];
#pragma unroll
            for (int r = 0; r < 8; r++)
#pragma unroll
                for (int c = 0; c < 4; c++)
                    acc[r][c] = fmaf(a[r], bb[c], acc[r][c]);
        }
    }
#pragma unroll
    for (int r = 0; r < 8; r++) {
        int s = s0 + (ty << 3) + r;
        float4 o;
        o.x = acc[r][0]; o.y = acc[r][1]; o.z = acc[r][2]; o.w = acc[r][3];
        *(float4*)&g_awv[((size_t)s * B_ + b) * HI_ + h * 64 + (tx << 2)] = o;
    }
}

// ---------------- LayerNorm over E=1024 ------------------------------------
__global__ __launch_bounds__(256) void ln_kernel(const float* __restrict__ gamma,
                                                 const float* __restrict__ beta,
                                                 float* __restrict__ out) {
    int row = blockIdx.x;
    const float* x = g_o + (size_t)row * E_;
    int tid = threadIdx.x;
    float4 v = *(const float4*)&x[tid << 2];
    float s1 = v.x + v.y + v.z + v.w;
    float s2 = v.x * v.x + v.y * v.y + v.z * v.z + v.w * v.w;
    __shared__ float r1[8], r2[8];
#pragma unroll
    for (int o = 16; o > 0; o >>= 1) {
        s1 += __shfl_xor_sync(0xffffffffu, s1, o);
        s2 += __shfl_xor_sync(0xffffffffu, s2, o);
    }
    if ((tid & 31) == 0) { r1[tid >> 5] = s1; r2[tid >> 5] = s2; }
    __syncthreads();
    float S1 = 0.f, S2 = 0.f;
#pragma unroll
    for (int i = 0; i < 8; i++) { S1 += r1[i]; S2 += r2[i]; }
    float mean = S1 * (1.0f / E_);
    float var = S2 * (1.0f / E_) - mean * mean;
    float rstd = rsqrtf(var + 1e-5f);
    float4 g = *(const float4*)&gamma[tid << 2];
    float4 bb = *(const float4*)&beta[tid << 2];
    float4 o;
    o.x = (v.x - mean) * rstd * g.x + bb.x;
    o.y = (v.y - mean) * rstd * g.y + bb.y;
    o.z = (v.z - mean) * rstd * g.z + bb.z;
    o.w = (v.w - mean) * rstd * g.w + bb.w;
    *(float4*)&out[(size_t)row * E_ + (tid << 2)] = o;
}

// ---------------- launch ----------------------------------------------------
extern "C" void kernel_launch(void* const* d_in, const int* in_sizes, int n_in,
                              void* d_out, int out_size) {
    (void)in_sizes; (void)n_in; (void)out_size;
    const float* inputMHA = (const float*)d_in[0];
    const float* posEmb   = (const float*)d_in[1];
    const float* memory   = (const float*)d_in[2];
    const float* u        = (const float*)d_in[3];
    const float* v        = (const float*)d_in[4];
    // d_in[5] = mask : computed analytically (j > P + s), never read
    const float* W_kv     = (const float*)d_in[6];
    const float* W_q      = (const float*)d_in[7];
    const float* W_p      = (const float*)d_in[8];
    const float* W_o      = (const float*)d_in[9];
    const float* gamma    = (const float*)d_in[10];
    const float* beta     = (const float*)d_in[11];

    float *pq, *pkv, *pp, *pawv, *po;
    cudaGetSymbolAddress((void**)&pq, g_q);
    cudaGetSymbolAddress((void**)&pkv, g_kv);
    cudaGetSymbolAddress((void**)&pp, g_p);
    cudaGetSymbolAddress((void**)&pawv, g_awv);
    cudaGetSymbolAddress((void**)&po, g_o);

    cudaFuncSetAttribute(scores_kernel, cudaFuncAttributeMaxDynamicSharedMemorySize,
                         SC_SMEM_BYTES);

    // q = inputMHA @ W_q                       (4096 x 1024 x 1024)
    sgemm128<<<dim3(HI_ / 128, (S_ * B_) / 128), 256>>>(inputMHA, W_q, nullptr, pq,
                                                        S_ * B_, HI_, E_);
    // kv = [memory ; inputMHA] @ W_kv          (8192 x 2048 x 1024, two halves)
    sgemm128<<<dim3((2 * HI_) / 128, (P_ * B_) / 128), 256>>>(memory, W_kv, nullptr, pkv,
                                                              P_ * B_, 2 * HI_, E_);
    sgemm128<<<dim3((2 * HI_) / 128, (S_ * B_) / 128), 256>>>(
        inputMHA, W_kv, nullptr, pkv + (size_t)P_ * B_ * 2 * HI_, S_ * B_, 2 * HI_, E_);
    // p = posEmbeddings @ W_p                  (2048 x 1024 x 1024)
    sgemm128<<<dim3(HI_ / 128, J_ / 128), 256>>>(posEmb, W_p, nullptr, pp, J_, HI_, E_);

    // fused content+position logits with analytic rel-shift + mask + scale
    scores_kernel<<<dim3(J_ / 64, S_ / 64, B_ * H_), 256, SC_SMEM_BYTES>>>(u, v);

    // softmax over keys
    softmax_kernel<<<dim3(S_, B_ * H_), 256>>>();

    // awv = probs @ V
    awv_kernel<<<dim3(S_ / 128, B_ * H_), 256>>>();

    // out = inputMHA + awv @ W_o
    sgemm128<<<dim3(E_ / 128, (S_ * B_) / 128), 256>>>(pawv, W_o, inputMHA, po,
                                                       S_ * B_, E_, HI_);
    // LayerNorm -> d_out
    ln_kernel<<<S_ * B_, 256>>>(gamma, beta, (float*)d_out);
}

// round 4
// speedup vs baseline: 1.2691x; 1.2691x over previous
#include <cuda_runtime.h>
#include <cuda_bf16.h>
#include <cstdint>
#include <cstddef>

#define S_  1024
#define P_  1024
#define J_  2048
#define B_  4
#define E_  1024
#define H_  16
#define I_  64
#define HI_ 1024

// ---------------- fp32 scratch ----------------------------------------------
__device__ float g_q[(size_t)S_ * B_ * HI_];          // (S,B,H*I)
__device__ float g_kv[(size_t)J_ * B_ * 2 * HI_];     // (J,B,2*H*I)  keys | values
__device__ float g_p[(size_t)J_ * HI_];               // (J,H*I)
__device__ float g_sc[(size_t)B_ * H_ * S_ * J_];     // (B*H, S, J) logits -> probs
__device__ float g_awv[(size_t)S_ * B_ * HI_];        // (S,B,H*I)
__device__ float g_o[(size_t)S_ * B_ * E_];           // pre-LN output

// ---------------- bf16-split scratch ----------------------------------------
__device__ __nv_bfloat16 g_xhi[(size_t)8192 * 1024];   // [memory ; inputMHA]
__device__ __nv_bfloat16 g_xlo[(size_t)8192 * 1024];
__device__ __nv_bfloat16 g_pehi[(size_t)2048 * 1024];  // posEmb
__device__ __nv_bfloat16 g_pelo[(size_t)2048 * 1024];
__device__ __nv_bfloat16 g_ahi[(size_t)4096 * 1024];   // awv
__device__ __nv_bfloat16 g_alo[(size_t)4096 * 1024];
__device__ __nv_bfloat16 g_wqhi[(size_t)1024 * 1024];  // W^T [N,K]
__device__ __nv_bfloat16 g_wqlo[(size_t)1024 * 1024];
__device__ __nv_bfloat16 g_wkvhi[(size_t)2048 * 1024];
__device__ __nv_bfloat16 g_wkvlo[(size_t)2048 * 1024];
__device__ __nv_bfloat16 g_wphi[(size_t)1024 * 1024];
__device__ __nv_bfloat16 g_wplo[(size_t)1024 * 1024];
__device__ __nv_bfloat16 g_wohi[(size_t)1024 * 1024];
__device__ __nv_bfloat16 g_wolo[(size_t)1024 * 1024];

// ---------------- small helpers ---------------------------------------------
__device__ __forceinline__ uint32_t smem_u32(const void* p) {
    uint32_t a;
    asm("{ .reg .u64 t; cvta.to.shared.u64 t, %1; cvt.u32.u64 %0, t; }"
        : "=r"(a) : "l"(p));
    return a;
}
__device__ __forceinline__ void cpa16(uint32_t s, const void* g) {
    asm volatile("cp.async.cg.shared.global [%0], [%1], 16;" :: "r"(s), "l"(g));
}
__device__ __forceinline__ void ldm_x4(uint32_t* d, uint32_t addr) {
    asm volatile("ldmatrix.sync.aligned.m8n8.x4.shared.b16 {%0,%1,%2,%3}, [%4];"
                 : "=r"(d[0]), "=r"(d[1]), "=r"(d[2]), "=r"(d[3]) : "r"(addr));
}
__device__ __forceinline__ void ldm_x2(uint32_t* d, uint32_t addr) {
    asm volatile("ldmatrix.sync.aligned.m8n8.x2.shared.b16 {%0,%1}, [%2];"
                 : "=r"(d[0]), "=r"(d[1]) : "r"(addr));
}
__device__ __forceinline__ void mma16816(float* c, const uint32_t* a, const uint32_t* b) {
    asm volatile("mma.sync.aligned.m16n8k16.row.col.f32.bf16.bf16.f32 "
                 "{%0,%1,%2,%3},{%4,%5,%6,%7},{%8,%9},{%0,%1,%2,%3};"
                 : "+f"(c[0]), "+f"(c[1]), "+f"(c[2]), "+f"(c[3])
                 : "r"(a[0]), "r"(a[1]), "r"(a[2]), "r"(a[3]), "r"(b[0]), "r"(b[1]));
}

// ---------------- HMMA bf16x3 GEMM: C[M,N] = A[M,K]*B[N,K]^T (+res) ---------
// CTA tile 128x128, 8 warps (warp tile 64x32), K-chunk 32, 3-stage cp.async.
#define ROWB   80          // padded row stride in bytes (32 bf16 + 8 pad)
#define TILEB  (128 * ROWB)  // 10240
#define STG    (4 * TILEB)   // Ahi,Alo,Bhi,Blo per stage = 40960
#define NSTG   3
#define GM_SMEM (NSTG * STG) // 122880

__device__ __forceinline__ void gload(uint32_t dst, const __nv_bfloat16* src,
                                      int row0, int ld, int k0, int tid) {
    // 128 rows x 64 bytes (4 x 16B chunks) -> padded smem
#pragma unroll
    for (int it = 0; it < 2; it++) {
        int idx = it * 256 + tid;
        int r = idx >> 2, c = idx & 3;
        cpa16(dst + r * ROWB + c * 16, src + (size_t)(row0 + r) * ld + k0 + c * 8);
    }
}

__global__ __launch_bounds__(256) void hmma_gemm(const __nv_bfloat16* __restrict__ Ahi,
                                                 const __nv_bfloat16* __restrict__ Alo,
                                                 const __nv_bfloat16* __restrict__ Bhi,
                                                 const __nv_bfloat16* __restrict__ Blo,
                                                 const float* __restrict__ res,
                                                 float* __restrict__ C,
                                                 int M, int N, int K) {
    extern __shared__ char smc[];
    uint32_t sb = smem_u32(smc);
    int tid = threadIdx.x, wid = tid >> 5, lane = tid & 31;
    int wm = wid & 1, wn = wid >> 1;            // warp grid 2 x 4
    int m0 = blockIdx.y * 128, n0 = blockIdx.x * 128;

    float acc[4][4][4];
#pragma unroll
    for (int t = 0; t < 4; t++)
#pragma unroll
        for (int s = 0; s < 4; s++)
#pragma unroll
            for (int r = 0; r < 4; r++) acc[t][s][r] = 0.f;

    const int NC = K / 32;
    // prologue: stages 0,1
#pragma unroll
    for (int st = 0; st < 2; st++) {
        uint32_t base = sb + st * STG;
        gload(base,             Ahi, m0, K, st * 32, tid);
        gload(base + TILEB,     Alo, m0, K, st * 32, tid);
        gload(base + 2 * TILEB, Bhi, n0, K, st * 32, tid);
        gload(base + 3 * TILEB, Blo, n0, K, st * 32, tid);
        asm volatile("cp.async.commit_group;" ::: "memory");
    }

    // per-thread ldmatrix address components
    int a_row = (lane & 15), a_hi16 = (lane >> 4) * 16;
    int b_row = (lane & 7), b_hi16 = ((lane >> 3) & 1) * 16;

    for (int c = 0; c < NC; c++) {
        if (c + 2 < NC) {
            uint32_t base = sb + ((c + 2) % NSTG) * STG;
            gload(base,             Ahi, m0, K, (c + 2) * 32, tid);
            gload(base + TILEB,     Alo, m0, K, (c + 2) * 32, tid);
            gload(base + 2 * TILEB, Bhi, n0, K, (c + 2) * 32, tid);
            gload(base + 3 * TILEB, Blo, n0, K, (c + 2) * 32, tid);
        }
        asm volatile("cp.async.commit_group;" ::: "memory");
        asm volatile("cp.async.wait_group 2;" ::: "memory");
        __syncthreads();

        uint32_t base = sb + (c % NSTG) * STG;
        uint32_t aH = base, aL = base + TILEB, bH = base + 2 * TILEB, bL = base + 3 * TILEB;
#pragma unroll
        for (int kk = 0; kk < 2; kk++) {
            uint32_t ah[4][4], al[4][4], bh[4][2], bl[4][2];
#pragma unroll
            for (int t = 0; t < 4; t++) {
                uint32_t off = (uint32_t)((wm * 64 + t * 16 + a_row) * ROWB + kk * 32 + a_hi16);
                ldm_x4(ah[t], aH + off);
                ldm_x4(al[t], aL + off);
            }
#pragma unroll
            for (int s = 0; s < 4; s++) {
                uint32_t off = (uint32_t)((wn * 32 + s * 8 + b_row) * ROWB + kk * 32 + b_hi16);
                ldm_x2(bh[s], bH + off);
                ldm_x2(bl[s], bL + off);
            }
#pragma unroll
            for (int t = 0; t < 4; t++)
#pragma unroll
                for (int s = 0; s < 4; s++) {
                    mma16816(acc[t][s], ah[t], bh[s]);
                    mma16816(acc[t][s], ah[t], bl[s]);
                    mma16816(acc[t][s], al[t], bh[s]);
                }
        }
        __syncthreads();
    }

    // epilogue: D frag mapping m16n8: d0,d1 @ (l>>2, (l&3)*2), d2,d3 @ (+8, same)
#pragma unroll
    for (int t = 0; t < 4; t++) {
        int mg = m0 + wm * 64 + t * 16 + (lane >> 2);
#pragma unroll
        for (int s = 0; s < 4; s++) {
            int ng = n0 + wn * 32 + s * 8 + (lane & 3) * 2;
            float2 v0 = make_float2(acc[t][s][0], acc[t][s][1]);
            float2 v1 = make_float2(acc[t][s][2], acc[t][s][3]);
            if (res) {
                float2 r0 = *(const float2*)&res[(size_t)mg * N + ng];
                float2 r1 = *(const float2*)&res[(size_t)(mg + 8) * N + ng];
                v0.x += r0.x; v0.y += r0.y; v1.x += r1.x; v1.y += r1.y;
            }
            *(float2*)&C[(size_t)mg * N + ng] = v0;
            *(float2*)&C[(size_t)(mg + 8) * N + ng] = v1;
        }
    }
}

// ---------------- fp32 -> bf16 hi/lo split ----------------------------------
__global__ __launch_bounds__(256) void split_kernel(const float* __restrict__ x,
                                                    __nv_bfloat16* __restrict__ hi,
                                                    __nv_bfloat16* __restrict__ lo,
                                                    int n) {
    int i = (blockIdx.x * 256 + threadIdx.x) * 4;
    if (i >= n) return;
    float4 v = *(const float4*)&x[i];
    __nv_bfloat162 h0, h1, l0, l1;
    h0.x = __float2bfloat16(v.x); h0.y = __float2bfloat16(v.y);
    h1.x = __float2bfloat16(v.z); h1.y = __float2bfloat16(v.w);
    l0.x = __float2bfloat16(v.x - __bfloat162float(h0.x));
    l0.y = __float2bfloat16(v.y - __bfloat162float(h0.y));
    l1.x = __float2bfloat16(v.z - __bfloat162float(h1.x));
    l1.y = __float2bfloat16(v.w - __bfloat162float(h1.y));
    *(__nv_bfloat162*)&hi[i] = h0;
    *(__nv_bfloat162*)&hi[i + 2] = h1;
    *(__nv_bfloat162*)&lo[i] = l0;
    *(__nv_bfloat162*)&lo[i + 2] = l1;
}

// ---------------- W[K,N] -> T[N,K] transpose + split ------------------------
__global__ void tsplit_kernel(const float* __restrict__ W,
                              __nv_bfloat16* __restrict__ Thi,
                              __nv_bfloat16* __restrict__ Tlo,
                              int Kd, int Nd) {
    __shared__ float t[32][33];
    int n0 = blockIdx.x * 32, k0 = blockIdx.y * 32;
    int tx = threadIdx.x, ty = threadIdx.y;
#pragma unroll
    for (int r = 0; r < 32; r += 8)
        t[ty + r][tx] = W[(size_t)(k0 + ty + r) * Nd + n0 + tx];
    __syncthreads();
#pragma unroll
    for (int r = 0; r < 32; r += 8) {
        float v = t[tx][ty + r];
        __nv_bfloat16 h = __float2bfloat16(v);
        Thi[(size_t)(n0 + ty + r) * Kd + k0 + tx] = h;
        Tlo[(size_t)(n0 + ty + r) * Kd + k0 + tx] =
            __float2bfloat16(v - __bfloat162float(h));
    }
}

// ---------------- scores: content + rel-shifted position, mask, scale ------
#define SC_SMEM_FLOATS (2 * 64 * 65 + 128 * 65 + 64)
#define SC_SMEM_BYTES  (SC_SMEM_FLOATS * 4)

__global__ __launch_bounds__(256) void scores_kernel(const float* __restrict__ u,
                                                     const float* __restrict__ vvec) {
    int bh = blockIdx.z;
    int b = bh >> 4, h = bh & 15;
    int s0 = blockIdx.y << 6, j0 = blockIdx.x << 6;
    int tid = threadIdx.x;
    float* out = g_sc + ((size_t)bh * S_ + s0) * J_ + j0;

    if (j0 > P_ + s0 + 63) {
        float4 m4 = make_float4(-1e30f, -1e30f, -1e30f, -1e30f);
#pragma unroll
        for (int it = 0; it < 4; it++) {
            int idx = it * 256 + tid;
            int r = idx >> 4, c = (idx & 15) << 2;
            *(float4*)&out[(size_t)r * J_ + c] = m4;
        }
        return;
    }

    extern __shared__ float smf[];
    float* qu_s = smf;
    float* K_s  = smf + 64 * 65;
    float* p_s  = smf + 2 * 64 * 65;
    float* w_s  = smf + 2 * 64 * 65 + 128 * 65;

    if (tid < 64) w_s[tid] = vvec[h * 64 + tid] - u[h * 64 + tid];

#pragma unroll
    for (int it = 0; it < 4; it++) {
        int idx = it * 256 + tid;
        int r = idx >> 4, i4 = (idx & 15) << 2;
        float4 q4 = *(const float4*)&g_q[((size_t)(s0 + r) * B_ + b) * HI_ + h * 64 + i4];
        float4 u4 = *(const float4*)&u[h * 64 + i4];
        qu_s[r * 65 + i4 + 0] = q4.x + u4.x;
        qu_s[r * 65 + i4 + 1] = q4.y + u4.y;
        qu_s[r * 65 + i4 + 2] = q4.z + u4.z;
        qu_s[r * 65 + i4 + 3] = q4.w + u4.w;
        float4 k4 = *(const float4*)&g_kv[((size_t)(j0 + r) * B_ + b) * (2 * HI_) + h * 64 + i4];
        K_s[r * 65 + i4 + 0] = k4.x;
        K_s[r * 65 + i4 + 1] = k4.y;
        K_s[r * 65 + i4 + 2] = k4.z;
        K_s[r * 65 + i4 + 3] = k4.w;
    }
    int d0 = j0 - s0 + 960;
#pragma unroll
    for (int it = 0; it < 8; it++) {
        int idx = it * 256 + tid;
        int r = idx >> 4, i4 = (idx & 15) << 2;
        int d = d0 + r;
        float4 p4 = make_float4(0.f, 0.f, 0.f, 0.f);
        if (d >= 0 && d < J_)
            p4 = *(const float4*)&g_p[(size_t)d * HI_ + h * 64 + i4];
        p_s[r * 65 + i4 + 0] = p4.x;
        p_s[r * 65 + i4 + 1] = p4.y;
        p_s[r * 65 + i4 + 2] = p4.z;
        p_s[r * 65 + i4 + 3] = p4.w;
    }
    __syncthreads();

    int tx = tid & 15, ty = tid >> 4;
    float acc[4][4];
#pragma unroll
    for (int r = 0; r < 4; r++)
#pragma unroll
        for (int c = 0; c < 4; c++) acc[r][c] = 0.f;

    int pb = (tx << 2) - (ty << 2) + 60;

    for (int i = 0; i < 64; i++) {
        float a[4], av[4], k[4], pv[7];
        float w = w_s[i];
#pragma unroll
        for (int r = 0; r < 4; r++) {
            a[r] = qu_s[((ty << 2) + r) * 65 + i];
            av[r] = a[r] + w;
        }
#pragma unroll
        for (int c = 0; c < 4; c++) k[c] = K_s[((tx << 2) + c) * 65 + i];
#pragma unroll
        for (int d = 0; d < 7; d++) pv[d] = p_s[(pb + d) * 65 + i];
#pragma unroll
        for (int r = 0; r < 4; r++)
#pragma unroll
            for (int c = 0; c < 4; c++)
                acc[r][c] = fmaf(a[r], k[c], fmaf(av[r], pv[c - r + 3], acc[r][c]));
    }

#pragma unroll
    for (int r = 0; r < 4; r++) {
        int s = s0 + (ty << 2) + r;
        int jb = j0 + (tx << 2);
        float4 o4;
        float* po = (float*)&o4;
#pragma unroll
        for (int c = 0; c < 4; c++)
            po[c] = (jb + c <= P_ + s) ? acc[r][c] * 0.125f : -1e30f;
        *(float4*)&out[(size_t)((ty << 2) + r) * J_ + (tx << 2)] = o4;
    }
}

// ---------------- row softmax over J=2048 ----------------------------------
__global__ __launch_bounds__(256) void softmax_kernel() {
    float* row = g_sc + ((size_t)blockIdx.y * S_ + blockIdx.x) * J_;
    int tid = threadIdx.x;
    float4 v0 = *(float4*)&row[tid * 8];
    float4 v1 = *(float4*)&row[tid * 8 + 4];
    float m = fmaxf(fmaxf(fmaxf(v0.x, v0.y), fmaxf(v0.z, v0.w)),
                    fmaxf(fmaxf(v1.x, v1.y), fmaxf(v1.z, v1.w)));
    __shared__ float red[8];
#pragma unroll
    for (int o = 16; o > 0; o >>= 1) m = fmaxf(m, __shfl_xor_sync(0xffffffffu, m, o));
    if ((tid & 31) == 0) red[tid >> 5] = m;
    __syncthreads();
    m = red[0];
#pragma unroll
    for (int i = 1; i < 8; i++) m = fmaxf(m, red[i]);

    v0.x = __expf(v0.x - m); v0.y = __expf(v0.y - m);
    v0.z = __expf(v0.z - m); v0.w = __expf(v0.w - m);
    v1.x = __expf(v1.x - m); v1.y = __expf(v1.y - m);
    v1.z = __expf(v1.z - m); v1.w = __expf(v1.w - m);
    float s = v0.x + v0.y + v0.z + v0.w + v1.x + v1.y + v1.z + v1.w;
    __syncthreads();
#pragma unroll
    for (int o = 16; o > 0; o >>= 1) s += __shfl_xor_sync(0xffffffffu, s, o);
    if ((tid & 31) == 0) red[tid >> 5] = s;
    __syncthreads();
    s = 0.f;
#pragma unroll
    for (int i = 0; i < 8; i++) s += red[i];
    float inv = 1.0f / s;
    v0.x *= inv; v0.y *= inv; v0.z *= inv; v0.w *= inv;
    v1.x *= inv; v1.y *= inv; v1.z *= inv; v1.w *= inv;
    *(float4*)&row[tid * 8] = v0;
    *(float4*)&row[tid * 8 + 4] = v1;
}

// ---------------- awv = probs @ V -------------------------------------------
__global__ __launch_bounds__(256) void awv_kernel() {
    int bh = blockIdx.y;
    int b = bh >> 4, h = bh & 15;
    int s0 = blockIdx.x << 7;
    int tid = threadIdx.x;
    int tx = tid & 15, ty = tid >> 4;
    __shared__ float Ps[16 * 132];
    __shared__ float Vs[16 * 68];
    float acc[8][4];
#pragma unroll
    for (int r = 0; r < 8; r++)
#pragma unroll
        for (int c = 0; c < 4; c++) acc[r][c] = 0.f;

    const float* Prow = g_sc + ((size_t)bh * S_ + s0) * J_;
    int kmax = P_ + s0 + 128;

    for (int j0 = 0; j0 < kmax; j0 += 16) {
        __syncthreads();
#pragma unroll
        for (int it = 0; it < 2; it++) {
            int idx = it * 256 + tid;
            int sr = idx >> 2, j4 = (idx & 3) << 2;
            float4 p4 = *(const float4*)&Prow[(size_t)sr * J_ + j0 + j4];
            Ps[(j4 + 0) * 132 + sr] = p4.x;
            Ps[(j4 + 1) * 132 + sr] = p4.y;
            Ps[(j4 + 2) * 132 + sr] = p4.z;
            Ps[(j4 + 3) * 132 + sr] = p4.w;
        }
        {
            int jr = tid >> 4, i4 = (tid & 15) << 2;
            float4 v4 = *(const float4*)&g_kv[((size_t)(j0 + jr) * B_ + b) * (2 * HI_) + HI_ + h * 64 + i4];
            *(float4*)&Vs[jr * 68 + i4] = v4;
        }
        __syncthreads();
#pragma unroll
        for (int jj = 0; jj < 16; jj++) {
            float a[8], bb[4];
            *(float4*)(a)     = *(const float4*)&Ps[jj * 132 + (ty << 3)];
            *(float4*)(a + 4) = *(const float4*)&Ps[jj * 132 + (ty << 3) + 4];
            *(float4*)(bb)    = *(const float4*)&Vs[jj * 68 + (tx << 2)];
#pragma unroll
            for (int r = 0; r < 8; r++)
#pragma unroll
                for (int c = 0; c < 4; c++)
                    acc[r][c] = fmaf(a[r], bb[c], acc[r][c]);
        }
    }
#pragma unroll
    for (int r = 0; r < 8; r++) {
        int s = s0 + (ty << 3) + r;
        float4 o;
        o.x = acc[r][0]; o.y = acc[r][1]; o.z = acc[r][2]; o.w = acc[r][3];
        *(float4*)&g_awv[((size_t)s * B_ + b) * HI_ + h * 64 + (tx << 2)] = o;
    }
}

// ---------------- LayerNorm over E=1024 ------------------------------------
__global__ __launch_bounds__(256) void ln_kernel(const float* __restrict__ gamma,
                                                 const float* __restrict__ beta,
                                                 float* __restrict__ out) {
    int row = blockIdx.x;
    const float* x = g_o + (size_t)row * E_;
    int tid = threadIdx.x;
    float4 v = *(const float4*)&x[tid << 2];
    float s1 = v.x + v.y + v.z + v.w;
    float s2 = v.x * v.x + v.y * v.y + v.z * v.z + v.w * v.w;
    __shared__ float r1[8], r2[8];
#pragma unroll
    for (int o = 16; o > 0; o >>= 1) {
        s1 += __shfl_xor_sync(0xffffffffu, s1, o);
        s2 += __shfl_xor_sync(0xffffffffu, s2, o);
    }
    if ((tid & 31) == 0) { r1[tid >> 5] = s1; r2[tid >> 5] = s2; }
    __syncthreads();
    float S1 = 0.f, S2 = 0.f;
#pragma unroll
    for (int i = 0; i < 8; i++) { S1 += r1[i]; S2 += r2[i]; }
    float mean = S1 * (1.0f / E_);
    float var = S2 * (1.0f / E_) - mean * mean;
    float rstd = rsqrtf(var + 1e-5f);
    float4 g = *(const float4*)&gamma[tid << 2];
    float4 bb = *(const float4*)&beta[tid << 2];
    float4 o;
    o.x = (v.x - mean) * rstd * g.x + bb.x;
    o.y = (v.y - mean) * rstd * g.y + bb.y;
    o.z = (v.z - mean) * rstd * g.z + bb.z;
    o.w = (v.w - mean) * rstd * g.w + bb.w;
    *(float4*)&out[(size_t)row * E_ + (tid << 2)] = o;
}

// ---------------- launch ----------------------------------------------------
extern "C" void kernel_launch(void* const* d_in, const int* in_sizes, int n_in,
                              void* d_out, int out_size) {
    (void)in_sizes; (void)n_in; (void)out_size;
    const float* inputMHA = (const float*)d_in[0];
    const float* posEmb   = (const float*)d_in[1];
    const float* memory   = (const float*)d_in[2];
    const float* u        = (const float*)d_in[3];
    const float* v        = (const float*)d_in[4];
    const float* W_kv     = (const float*)d_in[6];
    const float* W_q      = (const float*)d_in[7];
    const float* W_p      = (const float*)d_in[8];
    const float* W_o      = (const float*)d_in[9];
    const float* gamma    = (const float*)d_in[10];
    const float* beta     = (const float*)d_in[11];

    float *pq, *pkv, *pp, *pawv, *po;
    cudaGetSymbolAddress((void**)&pq, g_q);
    cudaGetSymbolAddress((void**)&pkv, g_kv);
    cudaGetSymbolAddress((void**)&pp, g_p);
    cudaGetSymbolAddress((void**)&pawv, g_awv);
    cudaGetSymbolAddress((void**)&po, g_o);

    __nv_bfloat16 *xhi, *xlo, *pehi, *pelo, *ahi, *alo;
    __nv_bfloat16 *wqh, *wql, *wkh, *wkl, *wph, *wpl, *woh, *wol;
    cudaGetSymbolAddress((void**)&xhi, g_xhi);
    cudaGetSymbolAddress((void**)&xlo, g_xlo);
    cudaGetSymbolAddress((void**)&pehi, g_pehi);
    cudaGetSymbolAddress((void**)&pelo, g_pelo);
    cudaGetSymbolAddress((void**)&ahi, g_ahi);
    cudaGetSymbolAddress((void**)&alo, g_alo);
    cudaGetSymbolAddress((void**)&wqh, g_wqhi);
    cudaGetSymbolAddress((void**)&wql, g_wqlo);
    cudaGetSymbolAddress((void**)&wkh, g_wkvhi);
    cudaGetSymbolAddress((void**)&wkl, g_wkvlo);
    cudaGetSymbolAddress((void**)&wph, g_wphi);
    cudaGetSymbolAddress((void**)&wpl, g_wplo);
    cudaGetSymbolAddress((void**)&woh, g_wohi);
    cudaGetSymbolAddress((void**)&wol, g_wolo);

    cudaFuncSetAttribute(scores_kernel, cudaFuncAttributeMaxDynamicSharedMemorySize,
                         SC_SMEM_BYTES);
    cudaFuncSetAttribute(hmma_gemm, cudaFuncAttributeMaxDynamicSharedMemorySize, GM_SMEM);

    // ---- convert inputs to bf16 hi/lo ----
    split_kernel<<<4096, 256>>>(memory, xhi, xlo, P_ * B_ * E_);
    split_kernel<<<4096, 256>>>(inputMHA, xhi + (size_t)P_ * B_ * E_,
                                xlo + (size_t)P_ * B_ * E_, S_ * B_ * E_);
    split_kernel<<<2048, 256>>>(posEmb, pehi, pelo, J_ * E_);
    tsplit_kernel<<<dim3(HI_ / 32, E_ / 32), dim3(32, 8)>>>(W_q, wqh, wql, E_, HI_);
    tsplit_kernel<<<dim3(2 * HI_ / 32, E_ / 32), dim3(32, 8)>>>(W_kv, wkh, wkl, E_, 2 * HI_);
    tsplit_kernel<<<dim3(HI_ / 32, E_ / 32), dim3(32, 8)>>>(W_p, wph, wpl, E_, HI_);
    tsplit_kernel<<<dim3(E_ / 32, HI_ / 32), dim3(32, 8)>>>(W_o, woh, wol, HI_, E_);

    // ---- tensor-core linears (HMMA bf16x3) ----
    hmma_gemm<<<dim3(HI_ / 128, (S_ * B_) / 128), 256, GM_SMEM>>>(
        xhi + (size_t)P_ * B_ * E_, xlo + (size_t)P_ * B_ * E_,
        wqh, wql, nullptr, pq, S_ * B_, HI_, E_);
    hmma_gemm<<<dim3(2 * HI_ / 128, (J_ * B_) / 128), 256, GM_SMEM>>>(
        xhi, xlo, wkh, wkl, nullptr, pkv, J_ * B_, 2 * HI_, E_);
    hmma_gemm<<<dim3(HI_ / 128, J_ / 128), 256, GM_SMEM>>>(
        pehi, pelo, wph, wpl, nullptr, pp, J_, HI_, E_);

    // ---- attention ----
    scores_kernel<<<dim3(J_ / 64, S_ / 64, B_ * H_), 256, SC_SMEM_BYTES>>>(u, v);
    softmax_kernel<<<dim3(S_, B_ * H_), 256>>>();
    awv_kernel<<<dim3(S_ / 128, B_ * H_), 256>>>();

    // ---- output projection + residual ----
    split_kernel<<<4096, 256>>>(pawv, ahi, alo, S_ * B_ * HI_);
    hmma_gemm<<<dim3(E_ / 128, (S_ * B_) / 128), 256, GM_SMEM>>>(
        ahi, alo, woh, wol, inputMHA, po, S_ * B_, E_, HI_);

    // ---- LayerNorm ----
    ln_kernel<<<S_ * B_, 256>>>(gamma, beta, (float*)d_out);
}